// round 12
// baseline (speedup 1.0000x reference)
#include <cuda_runtime.h>
#include <cstdint>

// Problem constants
constexpr int LL    = 4096;
constexpr int NB    = 16;
constexpr int NCIN  = 128;
constexpr int NCOUT = 128;
constexpr int KTOT  = NCIN * LL;            // 524288
constexpr int NB2   = NB / 2;               // 8 batch pairs (f32x2 packing)

// GEMM blocking
constexpr int KS        = 512;              // k-split blocks (each within one channel)
constexpr int K_CHUNK   = KTOT / KS;        // 1024
constexpr int STAGE_K   = 256;              // k per smem stage
constexpr int NSTAGES   = K_CHUNK / STAGE_K;// 4
constexpr int ITERS     = K_CHUNK / 64;     // 16 compute iters (64 k each)
constexpr int TOW       = 8;                // outputs per warp
constexpr int TOB       = 64;               // outputs per block
constexpr int OGROUPS   = NCOUT / TOB;      // 2

// Scratch (allocation-free)
__device__ float g_part[NB * NCOUT * KS];   // 4 MB, layout [b*NCOUT+o][ks]

__device__ __forceinline__ unsigned long long dup_f32x2(float v) {
    unsigned long long r;
    asm("mov.b64 %0, {%1, %1};" : "=l"(r) : "f"(v));
    return r;
}
__device__ __forceinline__ void fma_f32x2(unsigned long long& d,
                                          unsigned long long a,
                                          unsigned long long b) {
    asm("fma.rn.f32x2 %0, %1, %2, %0;" : "+l"(d) : "l"(a), "l"(b));
}
__device__ __forceinline__ void add_f32x2(unsigned long long& d,
                                          unsigned long long a) {
    asm("add.rn.f32x2 %0, %0, %1;" : "+l"(d) : "l"(a));
}

// ---------------------------------------------------------------------------
// Fused GEMM: out[b,o] = sum_k x[b, rev(k)] * w[o, k], split-K over 512 blocks.
// The index reversal (circular correlation at lag 0) is applied during smem
// staging, done with 4-byte cp.async gathers (descending-contiguous sources).
// 8 warps x 8 outputs; batches packed pairwise into f32x2 accumulators.
// Warp b2s==warp stages batch-pair `warp`'s slice each stage.
// ---------------------------------------------------------------------------
__global__ __launch_bounds__(256, 1) void gemm_kernel(const float* __restrict__ x,
                                                      const float* __restrict__ w) {
    __shared__ __align__(16) float2 s_x[2][NB2][STAGE_K];   // 2 x 16 KB

    const int ks   = blockIdx.x;
    const int og   = blockIdx.y;
    const int tid  = threadIdx.x;
    const int warp = tid >> 5;
    const int lane = tid & 31;
    const int o0   = og * TOB + warp * TOW;
    const int kbase = ks * K_CHUNK;                 // within one channel (1024 | 4096)
    const int mbase = kbase & (LL - 1);

    // staging: this warp handles batch pair b2s = warp, channel ich
    const int ich = kbase >> 12;
    const float* __restrict__ xlo = x + ((size_t)(2 * warp) * NCIN + ich) * LL;
    const float* __restrict__ xhi = xlo + (size_t)KTOT;   // next batch, same channel

    const float2* __restrict__ w2 = reinterpret_cast<const float2*>(w);
    const size_t wrow = KTOT / 2;
    const int kg2base = (kbase >> 1) + lane;

    // stage S of x -> smem buffer BUF via 4B cp.async with reversal
#define PREF(S, BUF)                                                            \
    {                                                                           \
        const int M0 = LL - (mbase + (S) * STAGE_K);                            \
        _Pragma("unroll")                                                       \
        for (int e = 0; e < 8; e++) {                                           \
            int kk   = lane + 32 * e;                                           \
            int msrc = (M0 - kk) & (LL - 1);                                    \
            uint32_t dlo = (uint32_t)__cvta_generic_to_shared(                  \
                &s_x[BUF][warp][kk]);                                           \
            asm volatile("cp.async.ca.shared.global [%0], [%1], 4;\n"           \
                         :: "r"(dlo), "l"(xlo + msrc));                         \
            asm volatile("cp.async.ca.shared.global [%0], [%1], 4;\n"           \
                         :: "r"(dlo + 4), "l"(xhi + msrc));                     \
        }                                                                       \
        asm volatile("cp.async.commit_group;\n");                               \
    }

    // prologue: stage 0 + first w iter
    PREF(0, 0);

    float2 wv[2][TOW];
#pragma unroll
    for (int o = 0; o < TOW; o++)
        wv[0][o] = __ldg(&w2[(size_t)(o0 + o) * wrow + kg2base]);

    unsigned long long acc[NB2][TOW];
#pragma unroll
    for (int b = 0; b < NB2; b++)
#pragma unroll
        for (int o = 0; o < TOW; o++) acc[b][o] = 0ull;

    asm volatile("cp.async.wait_group 0;\n");
    __syncthreads();

#pragma unroll
    for (int g = 0; g < ITERS; g++) {
        const int s   = g >> 2;
        const int j   = g & 3;
        const int cur = g & 1;
        const int buf = s & 1;

        // kick off next x stage at the start of this stage's compute
        if (j == 0 && s + 1 < NSTAGES) PREF(s + 1, (s + 1) & 1);

        // prefetch next iter's w into the other register buffer
        if (g + 1 < ITERS) {
            const int kg2n = kg2base + (g + 1) * 32;
#pragma unroll
            for (int o = 0; o < TOW; o++)
                wv[(g + 1) & 1][o] = __ldg(&w2[(size_t)(o0 + o) * wrow + kg2n]);
        }

        const int kloc = (j * 32 + lane) * 2;

        ulonglong2 xv[NB2];
#pragma unroll
        for (int b = 0; b < NB2; b++)
            xv[b] = *reinterpret_cast<const ulonglong2*>(&s_x[buf][b][kloc]);

#pragma unroll
        for (int o = 0; o < TOW; o++) {
            unsigned long long wd0 = dup_f32x2(wv[cur][o].x);
            unsigned long long wd1 = dup_f32x2(wv[cur][o].y);
#pragma unroll
            for (int b = 0; b < NB2; b++) {
                fma_f32x2(acc[b][o], xv[b].x, wd0);
                fma_f32x2(acc[b][o], xv[b].y, wd1);
            }
        }

        // publish next stage at the end of this stage
        if (j == 3 && s + 1 < NSTAGES) {
            asm volatile("cp.async.wait_group 0;\n");
            __syncthreads();
        }
    }
#undef PREF

    // Value-splitting butterfly: 64 accs -> lane l ends with accs 2l, 2l+1
    // fully reduced over all 32 lanes.
    unsigned long long vals[64];
#pragma unroll
    for (int b = 0; b < NB2; b++)
#pragma unroll
        for (int o = 0; o < TOW; o++) vals[b * TOW + o] = acc[b][o];

#define RSTEP(OFF, CNT)                                                         \
    {                                                                           \
        const bool up = (lane & (OFF)) != 0;                                    \
        _Pragma("unroll")                                                       \
        for (int j2 = 0; j2 < (CNT); j2++) {                                    \
            unsigned long long send = up ? vals[j2] : vals[j2 + (CNT)];         \
            unsigned long long recv = __shfl_xor_sync(0xffffffffu, send, OFF);  \
            unsigned long long keep = up ? vals[j2 + (CNT)] : vals[j2];         \
            add_f32x2(keep, recv);                                              \
            vals[j2] = keep;                                                    \
        }                                                                       \
    }
    RSTEP(16, 32)
    RSTEP(8, 16)
    RSTEP(4, 8)
    RSTEP(2, 4)
    RSTEP(1, 2)
#undef RSTEP

#pragma unroll
    for (int j2 = 0; j2 < 2; j2++) {
        int a  = 2 * lane + j2;
        int b2 = a >> 3;                               // vals layout [b2][o]
        int o  = a & 7;
        int oo = o0 + o;
        float2 v;
        asm("mov.b64 {%0, %1}, %2;" : "=f"(v.x), "=f"(v.y) : "l"(vals[j2]));
        g_part[((size_t)(2 * b2)     * NCOUT + oo) * KS + ks] = v.x;
        g_part[((size_t)(2 * b2 + 1) * NCOUT + oo) * KS + ks] = v.y;
    }
}

// ---------------------------------------------------------------------------
// Deterministic reduction over k-splits + bias. One warp per output, coalesced.
// ---------------------------------------------------------------------------
__global__ void reduce_kernel(const float* __restrict__ bias,
                              float* __restrict__ out) {
    int gw   = (blockIdx.x * blockDim.x + threadIdx.x) >> 5;  // output index
    int lane = threadIdx.x & 31;
    if (gw >= NB * NCOUT) return;
    const float* p = g_part + (size_t)gw * KS;
    float s = 0.0f;
#pragma unroll
    for (int i = 0; i < KS / 32; i++) s += p[i * 32 + lane];
#pragma unroll
    for (int off = 16; off > 0; off >>= 1)
        s += __shfl_xor_sync(0xffffffffu, s, off);
    if (lane == 0) out[gw] = s + bias[gw & (NCOUT - 1)];
}

// ---------------------------------------------------------------------------
extern "C" void kernel_launch(void* const* d_in, const int* in_sizes, int n_in,
                              void* d_out, int out_size) {
    const float* x    = (const float*)d_in[0];   // [16, 128, 4096]
    const float* w    = (const float*)d_in[1];   // [128, 128, 4096]
    const float* bias = (const float*)d_in[2];   // [128]
    float* out = (float*)d_out;                  // [16, 128, 1]

    dim3 grid(KS, OGROUPS);
    gemm_kernel<<<grid, 256>>>(x, w);

    reduce_kernel<<<(NB * NCOUT * 32) / 256, 256>>>(bias, out);
}

// round 13
// speedup vs baseline: 1.0004x; 1.0004x over previous
#include <cuda_runtime.h>
#include <cstdint>

// Problem constants
constexpr int LL    = 4096;
constexpr int NB    = 16;
constexpr int NCIN  = 128;
constexpr int NCOUT = 128;
constexpr int KTOT  = NCIN * LL;            // 524288
constexpr int NB2   = NB / 2;               // 8 batch pairs (f32x2 packing)

// GEMM blocking
constexpr int KS        = 512;              // k-split blocks (each within one channel)
constexpr int K_CHUNK   = KTOT / KS;        // 1024
constexpr int STAGE_K   = 256;              // k per smem stage
constexpr int NSTAGES   = K_CHUNK / STAGE_K;// 4
constexpr int ITERS     = K_CHUNK / 64;     // 16 compute iters (64 k each)
constexpr int TOW       = 8;                // outputs per warp
constexpr int TOB       = 64;               // outputs per block
constexpr int OGROUPS   = NCOUT / TOB;      // 2

// Scratch (allocation-free)
__device__ float g_part[NB * NCOUT * KS];   // 4 MB, layout [b*NCOUT+o][ks]

__device__ __forceinline__ unsigned long long dup_f32x2(float v) {
    unsigned long long r;
    asm("mov.b64 %0, {%1, %1};" : "=l"(r) : "f"(v));
    return r;
}
__device__ __forceinline__ void fma_f32x2(unsigned long long& d,
                                          unsigned long long a,
                                          unsigned long long b) {
    asm("fma.rn.f32x2 %0, %1, %2, %0;" : "+l"(d) : "l"(a), "l"(b));
}
__device__ __forceinline__ void add_f32x2(unsigned long long& d,
                                          unsigned long long a) {
    asm("add.rn.f32x2 %0, %0, %1;" : "+l"(d) : "l"(a));
}

// ---------------------------------------------------------------------------
// Fused GEMM: out[b,o] = sum_k x[b, rev(k)] * w[o, k], split-K over 512 blocks.
// The index reversal (circular correlation at lag 0) is applied during smem
// staging, done with 4-byte cp.async gathers (descending-contiguous sources).
// 8 warps x 8 outputs; batches packed pairwise into f32x2 accumulators.
// Warp b2s==warp stages batch-pair `warp`'s slice each stage.
// ---------------------------------------------------------------------------
__global__ __launch_bounds__(256, 1) void gemm_kernel(const float* __restrict__ x,
                                                      const float* __restrict__ w) {
    __shared__ __align__(16) float2 s_x[2][NB2][STAGE_K];   // 2 x 16 KB

    const int ks   = blockIdx.x;
    const int og   = blockIdx.y;
    const int tid  = threadIdx.x;
    const int warp = tid >> 5;
    const int lane = tid & 31;
    const int o0   = og * TOB + warp * TOW;
    const int kbase = ks * K_CHUNK;                 // within one channel (1024 | 4096)
    const int mbase = kbase & (LL - 1);

    // staging: this warp handles batch pair b2s = warp, channel ich
    const int ich = kbase >> 12;
    const float* __restrict__ xlo = x + ((size_t)(2 * warp) * NCIN + ich) * LL;
    const float* __restrict__ xhi = xlo + (size_t)KTOT;   // next batch, same channel

    const float2* __restrict__ w2 = reinterpret_cast<const float2*>(w);
    const size_t wrow = KTOT / 2;
    const int kg2base = (kbase >> 1) + lane;

    // stage S of x -> smem buffer BUF via 4B cp.async with reversal
#define PREF(S, BUF)                                                            \
    {                                                                           \
        const int M0 = LL - (mbase + (S) * STAGE_K);                            \
        _Pragma("unroll")                                                       \
        for (int e = 0; e < 8; e++) {                                           \
            int kk   = lane + 32 * e;                                           \
            int msrc = (M0 - kk) & (LL - 1);                                    \
            uint32_t dlo = (uint32_t)__cvta_generic_to_shared(                  \
                &s_x[BUF][warp][kk]);                                           \
            asm volatile("cp.async.ca.shared.global [%0], [%1], 4;\n"           \
                         :: "r"(dlo), "l"(xlo + msrc));                         \
            asm volatile("cp.async.ca.shared.global [%0], [%1], 4;\n"           \
                         :: "r"(dlo + 4), "l"(xhi + msrc));                     \
        }                                                                       \
        asm volatile("cp.async.commit_group;\n");                               \
    }

    // prologue: stage 0 + first w iter
    PREF(0, 0);

    float2 wv[2][TOW];
#pragma unroll
    for (int o = 0; o < TOW; o++)
        wv[0][o] = __ldg(&w2[(size_t)(o0 + o) * wrow + kg2base]);

    unsigned long long acc[NB2][TOW];
#pragma unroll
    for (int b = 0; b < NB2; b++)
#pragma unroll
        for (int o = 0; o < TOW; o++) acc[b][o] = 0ull;

    asm volatile("cp.async.wait_group 0;\n");
    __syncthreads();

#pragma unroll
    for (int g = 0; g < ITERS; g++) {
        const int s   = g >> 2;
        const int j   = g & 3;
        const int cur = g & 1;
        const int buf = s & 1;

        // kick off next x stage at the start of this stage's compute
        if (j == 0 && s + 1 < NSTAGES) PREF(s + 1, (s + 1) & 1);

        // prefetch next iter's w into the other register buffer
        if (g + 1 < ITERS) {
            const int kg2n = kg2base + (g + 1) * 32;
#pragma unroll
            for (int o = 0; o < TOW; o++)
                wv[(g + 1) & 1][o] = __ldg(&w2[(size_t)(o0 + o) * wrow + kg2n]);
        }

        const int kloc = (j * 32 + lane) * 2;

        ulonglong2 xv[NB2];
#pragma unroll
        for (int b = 0; b < NB2; b++)
            xv[b] = *reinterpret_cast<const ulonglong2*>(&s_x[buf][b][kloc]);

#pragma unroll
        for (int o = 0; o < TOW; o++) {
            unsigned long long wd0 = dup_f32x2(wv[cur][o].x);
            unsigned long long wd1 = dup_f32x2(wv[cur][o].y);
#pragma unroll
            for (int b = 0; b < NB2; b++) {
                fma_f32x2(acc[b][o], xv[b].x, wd0);
                fma_f32x2(acc[b][o], xv[b].y, wd1);
            }
        }

        // publish next stage at the end of this stage
        if (j == 3 && s + 1 < NSTAGES) {
            asm volatile("cp.async.wait_group 0;\n");
            __syncthreads();
        }
    }
#undef PREF

    // Value-splitting butterfly: 64 accs -> lane l ends with accs 2l, 2l+1
    // fully reduced over all 32 lanes.
    unsigned long long vals[64];
#pragma unroll
    for (int b = 0; b < NB2; b++)
#pragma unroll
        for (int o = 0; o < TOW; o++) vals[b * TOW + o] = acc[b][o];

#define RSTEP(OFF, CNT)                                                         \
    {                                                                           \
        const bool up = (lane & (OFF)) != 0;                                    \
        _Pragma("unroll")                                                       \
        for (int j2 = 0; j2 < (CNT); j2++) {                                    \
            unsigned long long send = up ? vals[j2] : vals[j2 + (CNT)];         \
            unsigned long long recv = __shfl_xor_sync(0xffffffffu, send, OFF);  \
            unsigned long long keep = up ? vals[j2 + (CNT)] : vals[j2];         \
            add_f32x2(keep, recv);                                              \
            vals[j2] = keep;                                                    \
        }                                                                       \
    }
    RSTEP(16, 32)
    RSTEP(8, 16)
    RSTEP(4, 8)
    RSTEP(2, 4)
    RSTEP(1, 2)
#undef RSTEP

#pragma unroll
    for (int j2 = 0; j2 < 2; j2++) {
        int a  = 2 * lane + j2;
        int b2 = a >> 3;                               // vals layout [b2][o]
        int o  = a & 7;
        int oo = o0 + o;
        float2 v;
        asm("mov.b64 {%0, %1}, %2;" : "=f"(v.x), "=f"(v.y) : "l"(vals[j2]));
        g_part[((size_t)(2 * b2)     * NCOUT + oo) * KS + ks] = v.x;
        g_part[((size_t)(2 * b2 + 1) * NCOUT + oo) * KS + ks] = v.y;
    }
}

// ---------------------------------------------------------------------------
// Deterministic reduction over k-splits + bias. One warp per output, coalesced.
// ---------------------------------------------------------------------------
__global__ void reduce_kernel(const float* __restrict__ bias,
                              float* __restrict__ out) {
    int gw   = (blockIdx.x * blockDim.x + threadIdx.x) >> 5;  // output index
    int lane = threadIdx.x & 31;
    if (gw >= NB * NCOUT) return;
    const float* p = g_part + (size_t)gw * KS;
    float s = 0.0f;
#pragma unroll
    for (int i = 0; i < KS / 32; i++) s += p[i * 32 + lane];
#pragma unroll
    for (int off = 16; off > 0; off >>= 1)
        s += __shfl_xor_sync(0xffffffffu, s, off);
    if (lane == 0) out[gw] = s + bias[gw & (NCOUT - 1)];
}

// ---------------------------------------------------------------------------
extern "C" void kernel_launch(void* const* d_in, const int* in_sizes, int n_in,
                              void* d_out, int out_size) {
    const float* x    = (const float*)d_in[0];   // [16, 128, 4096]
    const float* w    = (const float*)d_in[1];   // [128, 128, 4096]
    const float* bias = (const float*)d_in[2];   // [128]
    float* out = (float*)d_out;                  // [16, 128, 1]

    dim3 grid(KS, OGROUPS);
    gemm_kernel<<<grid, 256>>>(x, w);

    reduce_kernel<<<(NB * NCOUT * 32) / 256, 256>>>(bias, out);
}

// round 14
// speedup vs baseline: 1.0053x; 1.0050x over previous
#include <cuda_runtime.h>
#include <cstdint>

// Problem constants
constexpr int LL    = 4096;
constexpr int NB    = 16;
constexpr int NCIN  = 128;
constexpr int NCOUT = 128;
constexpr int KTOT  = NCIN * LL;            // 524288
constexpr int NB2   = NB / 2;               // 8 batch pairs (f32x2 packing)

// GEMM blocking
constexpr int KS        = 512;              // k-split blocks (each within one channel)
constexpr int K_CHUNK   = KTOT / KS;        // 1024
constexpr int STAGE_K   = 256;              // k per smem stage
constexpr int NSTAGES   = K_CHUNK / STAGE_K;// 4
constexpr int ITERS     = K_CHUNK / 64;     // 16 compute iters (64 k each)
constexpr int TOW       = 8;                // outputs per warp
constexpr int TOB       = 64;               // outputs per block
constexpr int OGROUPS   = NCOUT / TOB;      // 2

// Scratch (allocation-free)
__device__ float g_part[NB * NCOUT * KS];   // 4 MB, layout [b*NCOUT+o][ks]

__device__ __forceinline__ unsigned long long dup_f32x2(float v) {
    unsigned long long r;
    asm("mov.b64 %0, {%1, %1};" : "=l"(r) : "f"(v));
    return r;
}
__device__ __forceinline__ void fma_f32x2(unsigned long long& d,
                                          unsigned long long a,
                                          unsigned long long b) {
    asm("fma.rn.f32x2 %0, %1, %2, %0;" : "+l"(d) : "l"(a), "l"(b));
}
__device__ __forceinline__ void add_f32x2(unsigned long long& d,
                                          unsigned long long a) {
    asm("add.rn.f32x2 %0, %0, %1;" : "+l"(d) : "l"(a));
}

// ---------------------------------------------------------------------------
// Fused GEMM: out[b,o] = sum_k x[b, rev(k)] * w[o, k], split-K over 512 blocks.
// The index reversal (circular correlation at lag 0) is applied during smem
// staging, done with 4-byte cp.async gathers (descending-contiguous sources).
// 8 warps x 8 outputs; batches packed pairwise into f32x2 accumulators.
// Warp b2s==warp stages batch-pair `warp`'s slice each stage.
// ---------------------------------------------------------------------------
__global__ __launch_bounds__(256, 1) void gemm_kernel(const float* __restrict__ x,
                                                      const float* __restrict__ w) {
    __shared__ __align__(16) float2 s_x[2][NB2][STAGE_K];   // 2 x 16 KB

    const int ks   = blockIdx.x;
    const int og   = blockIdx.y;
    const int tid  = threadIdx.x;
    const int warp = tid >> 5;
    const int lane = tid & 31;
    const int o0   = og * TOB + warp * TOW;
    const int kbase = ks * K_CHUNK;                 // within one channel (1024 | 4096)
    const int mbase = kbase & (LL - 1);

    // staging: this warp handles batch pair b2s = warp, channel ich
    const int ich = kbase >> 12;
    const float* __restrict__ xlo = x + ((size_t)(2 * warp) * NCIN + ich) * LL;
    const float* __restrict__ xhi = xlo + (size_t)KTOT;   // next batch, same channel

    const float2* __restrict__ w2 = reinterpret_cast<const float2*>(w);
    const size_t wrow = KTOT / 2;
    const int kg2base = (kbase >> 1) + lane;

    // stage S of x -> smem buffer BUF via 4B cp.async with reversal
#define PREF(S, BUF)                                                            \
    {                                                                           \
        const int M0 = LL - (mbase + (S) * STAGE_K);                            \
        _Pragma("unroll")                                                       \
        for (int e = 0; e < 8; e++) {                                           \
            int kk   = lane + 32 * e;                                           \
            int msrc = (M0 - kk) & (LL - 1);                                    \
            uint32_t dlo = (uint32_t)__cvta_generic_to_shared(                  \
                &s_x[BUF][warp][kk]);                                           \
            asm volatile("cp.async.ca.shared.global [%0], [%1], 4;\n"           \
                         :: "r"(dlo), "l"(xlo + msrc));                         \
            asm volatile("cp.async.ca.shared.global [%0], [%1], 4;\n"           \
                         :: "r"(dlo + 4), "l"(xhi + msrc));                     \
        }                                                                       \
        asm volatile("cp.async.commit_group;\n");                               \
    }

    // prologue: stage 0 + first w iter
    PREF(0, 0);

    float2 wv[2][TOW];
#pragma unroll
    for (int o = 0; o < TOW; o++)
        wv[0][o] = __ldg(&w2[(size_t)(o0 + o) * wrow + kg2base]);

    unsigned long long acc[NB2][TOW];
#pragma unroll
    for (int b = 0; b < NB2; b++)
#pragma unroll
        for (int o = 0; o < TOW; o++) acc[b][o] = 0ull;

    asm volatile("cp.async.wait_group 0;\n");
    __syncthreads();

#pragma unroll
    for (int g = 0; g < ITERS; g++) {
        const int s   = g >> 2;
        const int j   = g & 3;
        const int cur = g & 1;
        const int buf = s & 1;

        // kick off next x stage at the start of this stage's compute
        if (j == 0 && s + 1 < NSTAGES) PREF(s + 1, (s + 1) & 1);

        // prefetch next iter's w into the other register buffer
        if (g + 1 < ITERS) {
            const int kg2n = kg2base + (g + 1) * 32;
#pragma unroll
            for (int o = 0; o < TOW; o++)
                wv[(g + 1) & 1][o] = __ldg(&w2[(size_t)(o0 + o) * wrow + kg2n]);
        }

        const int kloc = (j * 32 + lane) * 2;

        ulonglong2 xv[NB2];
#pragma unroll
        for (int b = 0; b < NB2; b++)
            xv[b] = *reinterpret_cast<const ulonglong2*>(&s_x[buf][b][kloc]);

#pragma unroll
        for (int o = 0; o < TOW; o++) {
            unsigned long long wd0 = dup_f32x2(wv[cur][o].x);
            unsigned long long wd1 = dup_f32x2(wv[cur][o].y);
#pragma unroll
            for (int b = 0; b < NB2; b++) {
                fma_f32x2(acc[b][o], xv[b].x, wd0);
                fma_f32x2(acc[b][o], xv[b].y, wd1);
            }
        }

        // publish next stage at the end of this stage
        if (j == 3 && s + 1 < NSTAGES) {
            asm volatile("cp.async.wait_group 0;\n");
            __syncthreads();
        }
    }
#undef PREF

    // Value-splitting butterfly: 64 accs -> lane l ends with accs 2l, 2l+1
    // fully reduced over all 32 lanes.
    unsigned long long vals[64];
#pragma unroll
    for (int b = 0; b < NB2; b++)
#pragma unroll
        for (int o = 0; o < TOW; o++) vals[b * TOW + o] = acc[b][o];

#define RSTEP(OFF, CNT)                                                         \
    {                                                                           \
        const bool up = (lane & (OFF)) != 0;                                    \
        _Pragma("unroll")                                                       \
        for (int j2 = 0; j2 < (CNT); j2++) {                                    \
            unsigned long long send = up ? vals[j2] : vals[j2 + (CNT)];         \
            unsigned long long recv = __shfl_xor_sync(0xffffffffu, send, OFF);  \
            unsigned long long keep = up ? vals[j2 + (CNT)] : vals[j2];         \
            add_f32x2(keep, recv);                                              \
            vals[j2] = keep;                                                    \
        }                                                                       \
    }
    RSTEP(16, 32)
    RSTEP(8, 16)
    RSTEP(4, 8)
    RSTEP(2, 4)
    RSTEP(1, 2)
#undef RSTEP

#pragma unroll
    for (int j2 = 0; j2 < 2; j2++) {
        int a  = 2 * lane + j2;
        int b2 = a >> 3;                               // vals layout [b2][o]
        int o  = a & 7;
        int oo = o0 + o;
        float2 v;
        asm("mov.b64 {%0, %1}, %2;" : "=f"(v.x), "=f"(v.y) : "l"(vals[j2]));
        g_part[((size_t)(2 * b2)     * NCOUT + oo) * KS + ks] = v.x;
        g_part[((size_t)(2 * b2 + 1) * NCOUT + oo) * KS + ks] = v.y;
    }
}

// ---------------------------------------------------------------------------
// Deterministic reduction over k-splits + bias. One warp per output, coalesced.
// ---------------------------------------------------------------------------
__global__ void reduce_kernel(const float* __restrict__ bias,
                              float* __restrict__ out) {
    int gw   = (blockIdx.x * blockDim.x + threadIdx.x) >> 5;  // output index
    int lane = threadIdx.x & 31;
    if (gw >= NB * NCOUT) return;
    const float* p = g_part + (size_t)gw * KS;
    float s = 0.0f;
#pragma unroll
    for (int i = 0; i < KS / 32; i++) s += p[i * 32 + lane];
#pragma unroll
    for (int off = 16; off > 0; off >>= 1)
        s += __shfl_xor_sync(0xffffffffu, s, off);
    if (lane == 0) out[gw] = s + bias[gw & (NCOUT - 1)];
}

// ---------------------------------------------------------------------------
extern "C" void kernel_launch(void* const* d_in, const int* in_sizes, int n_in,
                              void* d_out, int out_size) {
    const float* x    = (const float*)d_in[0];   // [16, 128, 4096]
    const float* w    = (const float*)d_in[1];   // [128, 128, 4096]
    const float* bias = (const float*)d_in[2];   // [128]
    float* out = (float*)d_out;                  // [16, 128, 1]

    dim3 grid(KS, OGROUPS);
    gemm_kernel<<<grid, 256>>>(x, w);

    reduce_kernel<<<(NB * NCOUT * 32) / 256, 256>>>(bias, out);
}